// round 16
// baseline (speedup 1.0000x reference)
#include <cuda_runtime.h>
#include <math.h>
#include <stdint.h>

#define IMG    64
#define NSLICE 16
#define NCOIL  4
#define NSING  4
#define NECHO  3
#define NRO    32
#define NPT    96
#define NEC    (NECHO * NCOIL)   // 12
#define NPIX   (IMG * IMG)       // 4096

// scf[kz][c][ne=n*3+e][pix]  (25 MB)   pixel index = X*64+Y (X major)
__device__ float2 g_scf[NSLICE * NCOIL * (NSING * NECHO) * NPIX];
// transposed singulars: tsing[ne][z][pix]  (6.3 MB)
__device__ float2 g_tsing[(NSING * NECHO) * NSLICE * NPIX];
// phase tables
__device__ float2 g_exp_[NRO * IMG * NPT];   // ex[r][x][p] = exp(-i*w0*(x-32))
__device__ float2 g_ey_[NRO * IMG * NPT];    // ey[r][y][p] = exp(-i*w1*(y-32))

// ---------------------------------------------------------------------------
// helpers
// ---------------------------------------------------------------------------
__device__ __forceinline__ float tf32r(float f) {
    uint32_t u;
    asm("cvt.rn.tf32.f32 %0, %1;" : "=r"(u) : "f"(f));
    return __uint_as_float(u);
}
__device__ __forceinline__ void mma_tf32(float* d, const uint32_t* a, const uint32_t* b) {
    asm volatile(
        "mma.sync.aligned.m16n8k8.row.col.f32.tf32.tf32.f32 "
        "{%0,%1,%2,%3}, {%4,%5,%6,%7}, {%8,%9}, {%0,%1,%2,%3};"
        : "+f"(d[0]), "+f"(d[1]), "+f"(d[2]), "+f"(d[3])
        : "r"(a[0]), "r"(a[1]), "r"(a[2]), "r"(a[3]), "r"(b[0]), "r"(b[1]));
}

// packed-fragment A write: A[96 rows][128 k] -> [6 mt][16 kstep][32 lane] float4
__device__ __forceinline__ void awrite(float* dst, int p, int k, float v) {
    int mt = p >> 4, g = p & 7, hi = (p >> 3) & 1;
    int kstep = k >> 3, tg = k & 3, kh = (k >> 2) & 1;
    dst[((((mt * 16 + kstep) * 32) + g * 4 + tg) << 2) + kh * 2 + hi] = v;
}
// packed-fragment B write: B[128 rows][128 k] -> [16 ntile][16 kstep][34 pad] float2
__device__ __forceinline__ void bwrite(float* dst, int row, int k, float v) {
    int ntile = row >> 3, g = row & 7;
    int kstep = k >> 3, tg = k & 3, kh = (k >> 2) & 1;
    dst[((((ntile * 16 + kstep) * 34) + g * 4 + tg) << 1) + kh] = v;
}

// ---------------------------------------------------------------------------
// Transpose: singulars [pix][z][ne]{2} -> g_tsing [ne][z][pix]{2}
// ---------------------------------------------------------------------------
__global__ __launch_bounds__(256)
void transpose_kernel(const float* __restrict__ singulars)   // [64,64,16,4,3,2]
{
    __shared__ float sS[256][25];   // 24 floats + pad
    const int z  = blockIdx.y;
    const int pb = blockIdx.x * 256;
    const int t  = threadIdx.x;

    const float4* src = (const float4*)(singulars + (size_t)(pb + t) * 384 + z * 24);
#pragma unroll
    for (int q = 0; q < 6; ++q) {
        float4 f = src[q];
        sS[t][4 * q + 0] = f.x; sS[t][4 * q + 1] = f.y;
        sS[t][4 * q + 2] = f.z; sS[t][4 * q + 3] = f.w;
    }
    __syncthreads();

#pragma unroll
    for (int j = 0; j < 12; ++j) {
        g_tsing[((size_t)j * NSLICE + z) * NPIX + pb + t]
            = make_float2(sS[t][2 * j], sS[t][2 * j + 1]);
    }
}

// ---------------------------------------------------------------------------
// Stage A (radix-2 DIF over z), unchanged.
// ---------------------------------------------------------------------------
__global__ __launch_bounds__(256, 3)
void stageA_kernel(const float* __restrict__ smap)   // [4,64,64,16,2]
{
    __shared__ float2 T8[8][8];     // w8^(m z0)
    __shared__ float2 T8s[8][8];    // sign(z0) * w8^(m z0)
    __shared__ float2 tws[8];       // sign(z0) * w16^(z0)
    __shared__ float2 sSm[256][17]; // staged smap tile, padded

    const int pixb = blockIdx.x * 256;
    const int t    = threadIdx.x;
    const int pix  = pixb + t;
    const int j    = blockIdx.y;
    const int c    = j & 3;
    const int ne   = j >> 2;               // n*3+e

    if (t < 64) {
        int z0 = t >> 3, m = t & 7;
        float ang = -(2.0f * (float)M_PI / 8.0f) * (float)(m * z0);
        float s, co; sincosf(ang, &s, &co);
        T8[z0][m] = make_float2(co, s);
        float sgn = (z0 & 1) ? -1.0f : 1.0f;
        T8s[z0][m] = make_float2(co * sgn, s * sgn);
    }
    if (t < 8) {
        float ang = -(2.0f * (float)M_PI / 16.0f) * (float)t;
        float s, co; sincosf(ang, &s, &co);
        float sgn = (t & 1) ? -1.0f : 1.0f;
        tws[t] = make_float2(co * sgn, s * sgn);
    }
    {
        const float2* smap2 = (const float2*)(smap) + ((size_t)c * NPIX + pixb) * NSLICE;
        for (int i = t; i < 256 * NSLICE; i += 256)
            sSm[i >> 4][i & 15] = smap2[i];
    }
    __syncthreads();

    const float2* vsrc = g_tsing + (size_t)ne * NSLICE * NPIX + pix;

    float aEr[8], aEi[8], aOr[8], aOi[8];
#pragma unroll
    for (int m = 0; m < 8; ++m) { aEr[m] = 0.f; aEi[m] = 0.f; aOr[m] = 0.f; aOi[m] = 0.f; }

#pragma unroll
    for (int z0 = 0; z0 < 8; ++z0) {
        float2 v0 = vsrc[(size_t)z0 * NPIX];
        float2 v8 = vsrc[(size_t)(z0 + 8) * NPIX];
        float2 s0 = sSm[t][z0];
        float2 s8 = sSm[t][z0 + 8];

        float t0r = v0.x * s0.x - v0.y * s0.y;
        float t0i = v0.x * s0.y + v0.y * s0.x;
        float t8r = v8.x * s8.x - v8.y * s8.y;
        float t8i = v8.x * s8.y + v8.y * s8.x;

        float ar  = t0r + t8r, ai = t0i + t8i;
        float bpr = t0r - t8r, bpi = t0i - t8i;
        float2 tw = tws[z0];
        float br = bpr * tw.x - bpi * tw.y;
        float bi = bpr * tw.y + bpi * tw.x;

#pragma unroll
        for (int m = 0; m < 8; ++m) {
            float2 wE = T8s[z0][m];
            aEr[m] = fmaf(ar, wE.x, aEr[m]);  aEr[m] = fmaf(-ai, wE.y, aEr[m]);
            aEi[m] = fmaf(ar, wE.y, aEi[m]);  aEi[m] = fmaf( ai, wE.x, aEi[m]);
            float2 wO = T8[z0][m];
            aOr[m] = fmaf(br, wO.x, aOr[m]);  aOr[m] = fmaf(-bi, wO.y, aOr[m]);
            aOi[m] = fmaf(br, wO.y, aOi[m]);  aOi[m] = fmaf( bi, wO.x, aOi[m]);
        }
    }

#pragma unroll
    for (int m = 0; m < 8; ++m) {
        g_scf[(((size_t)(2 * m) * NCOIL + c) * 12 + ne) * NPIX + pix]
            = make_float2(aEr[m], aEi[m]);
        g_scf[(((size_t)(2 * m + 1) * NCOIL + c) * 12 + ne) * NPIX + pix]
            = make_float2(aOr[m], aOi[m]);
    }
}

// ---------------------------------------------------------------------------
// Phase tables. grid 32, block 384.
// ---------------------------------------------------------------------------
__global__ __launch_bounds__(384)
void exgen_kernel(const float* __restrict__ ktraj)   // [1,32,96,2]
{
    const int r = blockIdx.x;
    const int p = threadIdx.x % NPT;
    const int g = threadIdx.x / NPT;       // 0..3, 16 steps each
    const float w0 = ktraj[(r * NPT + p) * 2 + 0];
    const float w1 = ktraj[(r * NPT + p) * 2 + 1];

    {
        float s, c; sincosf(w0, &s, &c);                      // step exp(-i*w0)
        float pr, pi; sincosf(w0 * (32.0f - g * 16.0f), &pi, &pr);
#pragma unroll 4
        for (int jj = 0; jj < 16; ++jj) {
            int x = g * 16 + jj;
            g_exp_[((size_t)r * IMG + x) * NPT + p] = make_float2(pr, pi);
            float t = pr;
            pr = fmaf(pr, c, pi * s);
            pi = fmaf(pi, c, -(t * s));
        }
    }
    {
        float s, c; sincosf(w1, &s, &c);
        float pr, pi; sincosf(w1 * (32.0f - g * 16.0f), &pi, &pr);
#pragma unroll 4
        for (int jj = 0; jj < 16; ++jj) {
            int y = g * 16 + jj;
            g_ey_[((size_t)r * IMG + y) * NPT + p] = make_float2(pr, pi);
            float t = pr;
            pr = fmaf(pr, c, pi * s);
            pi = fmaf(pi, c, -(t * s));
        }
    }
}

// ---------------------------------------------------------------------------
// NUFFT via warp-level mma.sync (tf32), 1024 threads (32 warps) per block:
//   m-split 2 x n-split 16; each warp 3m x 1n tiles, K = 16 k8 steps.
//   Fragment-packed A (LDS.128) / B (LDS.64); double-buffered B with
//   register prefetch; C overlays the retiring B buffer.
// grid (32 r, 4 ecg).  smem ~190KB -> 1 block/SM but 32 warps hide latency.
// ---------------------------------------------------------------------------
#define A_FL   (6 * 16 * 32 * 4)      // 12288 floats (48KB)
#define B_FL   (16 * 16 * 34 * 2)     // 17408 floats (68KB)
#define CS     132                    // C row stride (overlay, fits in B_FL)

__global__ __launch_bounds__(1024, 1)
void nufft_mma_kernel(const float* __restrict__ ur_list,   // [1,32,4]
                      const int*   __restrict__ sbin,      // [32]
                      float2* __restrict__ out)            // [96,4,32,3]
{
    extern __shared__ float sh[];
    float*  sA   = sh;                        // packed A
    float*  sB0  = sh + A_FL;                 // packed B buf 0
    float*  sB1  = sB0 + B_FL;                // packed B buf 1
    float2* sPar = (float2*)(sB1 + B_FL);     // [96][8]

    const int r    = blockIdx.x;
    const int ecg  = blockIdx.y;
    const int tid  = threadIdx.x;
    const int lane = tid & 31;
    const int w    = tid >> 5;      // 0..31
    const int mg   = w >> 4;        // 0..1  (m-rows 48*mg ..)
    const int ng   = w & 15;        // 0..15 (n-cols 8*ng ..)

    // ---- build A (tf32, packed): A[p][y] = ey.re, A[p][64+y] = -ey.im ----
    {
        const float2* gey = g_ey_ + (size_t)r * IMG * NPT;
        for (int i = tid; i < IMG * NPT; i += 1024) {
            int y = i / NPT, p = i % NPT;
            float2 e = gey[i];
            awrite(sA, p, y,      tf32r(e.x));
            awrite(sA, p, 64 + y, tf32r(-e.y));
        }
    }

    const int kzr = sbin[r];
    const float u0 = ur_list[r * NSING + 0];
    const float u1 = ur_list[r * NSING + 1];
    const float u2 = ur_list[r * NSING + 2];
    const float u3 = ur_list[r * NSING + 3];

    const float2* bases[3];
#pragma unroll
    for (int it = 0; it < 3; ++it) {
        int ec = ecg * 3 + it;
        bases[it] = g_scf + ((size_t)(kzr * NCOIL + (ec & 3)) * 12 + (ec >> 2)) * NPIX;
    }

    float mr[4], mi[4];   // prefetched+mixed image values for next B

#define LOAD_MIX(IT)                                                      \
    {                                                                     \
        const float2* base = bases[IT];                                   \
        _Pragma("unroll")                                                 \
        for (int jj = 0; jj < 4; ++jj) {                                  \
            int i = tid + jj * 1024;                                      \
            float2 s0 = base[i];                                          \
            float2 s1 = base[i + 3 * NPIX];                               \
            float2 s2 = base[i + 6 * NPIX];                               \
            float2 s3 = base[i + 9 * NPIX];                               \
            mr[jj] = fmaf(u0, s0.x, fmaf(u1, s1.x, fmaf(u2, s2.x, u3 * s3.x))); \
            mi[jj] = fmaf(u0, s0.y, fmaf(u1, s1.y, fmaf(u2, s2.y, u3 * s3.y))); \
        }                                                                 \
    }

    // B rows: [x] = [re | im], [64+x] = [im | -re]  (k = y, 64+y), packed
#define STORE_B(BUF)                                                      \
    {                                                                     \
        float* dst = (BUF);                                               \
        _Pragma("unroll")                                                 \
        for (int jj = 0; jj < 4; ++jj) {                                  \
            int i = tid + jj * 1024;                                      \
            int x = i >> 6, y = i & 63;                                   \
            float tar = tf32r(mr[jj]), tai = tf32r(mi[jj]);               \
            bwrite(dst, x,      y,      tar);                             \
            bwrite(dst, x,      64 + y, tai);                             \
            bwrite(dst, 64 + x, y,      tai);                             \
            bwrite(dst, 64 + x, 64 + y, tf32r(-mr[jj]));                  \
        }                                                                 \
    }

    // prologue
    LOAD_MIX(0);
    __syncthreads();          // A visible
    STORE_B(sB0);
    LOAD_MIX(1);              // prefetch ec1 (LDGs in flight through mma(0))
    __syncthreads();          // B0 visible

    const float4* sA4  = (const float4*)sA;
    const float2* gex  = g_exp_ + (size_t)r * IMG * NPT;

    for (int it = 0; it < 3; ++it) {
        const int ec = ecg * 3 + it;
        const int e  = ec >> 2;
        const int c  = ec & 3;
        float* bufc = (it & 1) ? sB1 : sB0;
        float* bufn = (it & 1) ? sB0 : sB1;
        const float2* sB2 = (const float2*)bufc;

        // ---- mma mainloop: K = 128 in 16 k8 steps, 3m x 1n tiles ----
        float d[3][4];
#pragma unroll
        for (int mt = 0; mt < 3; ++mt)
#pragma unroll
            for (int q = 0; q < 4; ++q) d[mt][q] = 0.f;

#pragma unroll
        for (int kstep = 0; kstep < 16; ++kstep) {
            uint32_t a[3][4], b[2];
#pragma unroll
            for (int mt = 0; mt < 3; ++mt) {
                float4 av = sA4[(((mg * 3 + mt) * 16 + kstep) << 5) + lane];
                a[mt][0] = __float_as_uint(av.x);
                a[mt][1] = __float_as_uint(av.y);
                a[mt][2] = __float_as_uint(av.z);
                a[mt][3] = __float_as_uint(av.w);
            }
            {
                float2 bv = sB2[(ng * 16 + kstep) * 34 + lane];
                b[0] = __float_as_uint(bv.x);
                b[1] = __float_as_uint(bv.y);
            }
#pragma unroll
            for (int mt = 0; mt < 3; ++mt)
                mma_tf32(d[mt], a[mt], b);
        }

        // write next B while mma results settle (prefetched regs)
        if (it < 2) STORE_B(bufn);
        if (it < 1) LOAD_MIX(2);     // prefetch last ec

        __syncthreads();   // mma reads of bufc done

        // ---- store C (t1) into bufc overlay: t1[p][ncol], rows 0..95 ----
        {
            const int g  = lane >> 2;
            const int tg = lane & 3;
            const int n  = ng * 8 + 2 * tg;
#pragma unroll
            for (int mt = 0; mt < 3; ++mt) {
                int p = mg * 48 + mt * 16 + g;
                bufc[p * CS + n]           = d[mt][0];
                bufc[p * CS + n + 1]       = d[mt][1];
                bufc[(p + 8) * CS + n]     = d[mt][2];
                bufc[(p + 8) * CS + n + 1] = d[mt][3];
            }
        }
        __syncthreads();

        // ---- ex contraction: thread (p, h) handles x in [8h, 8h+8) ----
        if (tid < 768) {
            int p = tid % 96, h = tid / 96;          // h 0..7
            float orr = 0.f, oii = 0.f;
            const float* rowp = bufc + p * CS;
#pragma unroll
            for (int x = 8 * h; x < 8 * h + 8; ++x) {
                float tr = rowp[x];
                float ti = rowp[64 + x];
                float2 ex = gex[x * NPT + p];
                orr = fmaf(tr,  ex.x, orr);
                orr = fmaf(-ti, ex.y, orr);
                oii = fmaf(tr,  ex.y, oii);
                oii = fmaf(ti,  ex.x, oii);
            }
            sPar[p * 8 + h] = make_float2(orr, oii);
        }
        __syncthreads();

        if (tid < NPT) {
            float sr = 0.f, si = 0.f;
#pragma unroll
            for (int q = 0; q < 8; ++q) {
                float2 v = sPar[tid * 8 + q];
                sr += v.x; si += v.y;
            }
            out[((tid * NCOIL + c) * NRO + r) * NECHO + e] = make_float2(sr, si);
        }
        __syncthreads();   // epilogue readers of bufc done before next STORE_B
    }
#undef LOAD_MIX
#undef STORE_B
}

// ---------------------------------------------------------------------------
extern "C" void kernel_launch(void* const* d_in, const int* in_sizes, int n_in,
                              void* d_out, int out_size)
{
    const float* singulars = (const float*)d_in[0];
    const float* smap      = (const float*)d_in[1];
    const float* ktraj     = (const float*)d_in[2];
    const float* ur_list   = (const float*)d_in[3];
    const int*   sbin      = (const int*)d_in[4];
    // d_in[5] = dc (unused by the forward reference)

    float2* out = (float2*)d_out;

    const int smemNufft = (A_FL + 2 * B_FL) * (int)sizeof(float)
                        + 96 * 8 * (int)sizeof(float2);    // ~190KB
    cudaFuncSetAttribute(nufft_mma_kernel,
                         cudaFuncAttributeMaxDynamicSharedMemorySize, smemNufft);

    transpose_kernel<<<dim3(16, 16), 256>>>(singulars);
    exgen_kernel<<<NRO, 384>>>(ktraj);
    stageA_kernel<<<dim3(16, 48), 256>>>(smap);
    nufft_mma_kernel<<<dim3(NRO, 4), 1024, smemNufft>>>(ur_list, sbin, out);
}

// round 17
// speedup vs baseline: 1.3081x; 1.3081x over previous
#include <cuda_runtime.h>
#include <cuda_fp16.h>
#include <math.h>
#include <stdint.h>

#define IMG    64
#define NSLICE 16
#define NCOIL  4
#define NSING  4
#define NECHO  3
#define NRO    32
#define NPT    96
#define NEC    (NECHO * NCOIL)   // 12
#define NPIX   (IMG * IMG)       // 4096

// scf[kz][c][ne=n*3+e][pix]  (25 MB)   pixel index = X*64+Y (X major)
__device__ float2 g_scf[NSLICE * NCOIL * (NSING * NECHO) * NPIX];
// transposed singulars: tsing[ne][z][pix]  (6.3 MB)
__device__ float2 g_tsing[(NSING * NECHO) * NSLICE * NPIX];
// phase tables
__device__ float2 g_exp_[NRO * IMG * NPT];   // ex[r][x][p] = exp(-i*w0*(x-32))
// packed fp16 A fragments per r: [6 mt][8 kstep][32 lane] uint4
__device__ uint4  g_eyA[NRO * 1536];

// ---------------------------------------------------------------------------
// helpers
// ---------------------------------------------------------------------------
__device__ __forceinline__ void mma_f16(float* d, const uint32_t* a, const uint32_t* b) {
    asm volatile(
        "mma.sync.aligned.m16n8k16.row.col.f32.f16.f16.f32 "
        "{%0,%1,%2,%3}, {%4,%5,%6,%7}, {%8,%9}, {%0,%1,%2,%3};"
        : "+f"(d[0]), "+f"(d[1]), "+f"(d[2]), "+f"(d[3])
        : "r"(a[0]), "r"(a[1]), "r"(a[2]), "r"(a[3]), "r"(b[0]), "r"(b[1]));
}

// packed A write (half2 granularity): A[96 rows][128 k], k0 even
__device__ __forceinline__ void awrite2g(__half2* baseA, int p, int k0, __half2 v) {
    int mt = p >> 4, gg = p & 7, hi = (p >> 3) & 1;
    int kstep = k0 >> 4, kh = (k0 >> 3) & 1, tg = (k0 >> 1) & 3;
    baseA[((((mt * 8 + kstep) * 32) + gg * 4 + tg) << 2) + kh * 2 + hi] = v;
}
// packed B write (half2): B[128 rows][128 k], k0 even; pad 36 uint2 per kstep
__device__ __forceinline__ void bwrite2(__half2* dst, int row, int k0, __half2 v) {
    int nt = row >> 3, gg = row & 7;
    int kstep = k0 >> 4, which = (k0 >> 3) & 1, tg = (k0 >> 1) & 3;
    dst[(((nt * 8 + kstep) * 36) + gg * 4 + tg) * 2 + which] = v;
}

// ---------------------------------------------------------------------------
// Transpose: singulars [pix][z][ne]{2} -> g_tsing [ne][z][pix]{2}
// ---------------------------------------------------------------------------
__global__ __launch_bounds__(256)
void transpose_kernel(const float* __restrict__ singulars)   // [64,64,16,4,3,2]
{
    __shared__ float sS[256][25];   // 24 floats + pad
    const int z  = blockIdx.y;
    const int pb = blockIdx.x * 256;
    const int t  = threadIdx.x;

    const float4* src = (const float4*)(singulars + (size_t)(pb + t) * 384 + z * 24);
#pragma unroll
    for (int q = 0; q < 6; ++q) {
        float4 f = src[q];
        sS[t][4 * q + 0] = f.x; sS[t][4 * q + 1] = f.y;
        sS[t][4 * q + 2] = f.z; sS[t][4 * q + 3] = f.w;
    }
    __syncthreads();

#pragma unroll
    for (int j = 0; j < 12; ++j) {
        g_tsing[((size_t)j * NSLICE + z) * NPIX + pb + t]
            = make_float2(sS[t][2 * j], sS[t][2 * j + 1]);
    }
}

// ---------------------------------------------------------------------------
// Stage A (radix-2 DIF over z), unchanged.
// ---------------------------------------------------------------------------
__global__ __launch_bounds__(256, 3)
void stageA_kernel(const float* __restrict__ smap)   // [4,64,64,16,2]
{
    __shared__ float2 T8[8][8];
    __shared__ float2 T8s[8][8];
    __shared__ float2 tws[8];
    __shared__ float2 sSm[256][17];

    const int pixb = blockIdx.x * 256;
    const int t    = threadIdx.x;
    const int pix  = pixb + t;
    const int j    = blockIdx.y;
    const int c    = j & 3;
    const int ne   = j >> 2;

    if (t < 64) {
        int z0 = t >> 3, m = t & 7;
        float ang = -(2.0f * (float)M_PI / 8.0f) * (float)(m * z0);
        float s, co; sincosf(ang, &s, &co);
        T8[z0][m] = make_float2(co, s);
        float sgn = (z0 & 1) ? -1.0f : 1.0f;
        T8s[z0][m] = make_float2(co * sgn, s * sgn);
    }
    if (t < 8) {
        float ang = -(2.0f * (float)M_PI / 16.0f) * (float)t;
        float s, co; sincosf(ang, &s, &co);
        float sgn = (t & 1) ? -1.0f : 1.0f;
        tws[t] = make_float2(co * sgn, s * sgn);
    }
    {
        const float2* smap2 = (const float2*)(smap) + ((size_t)c * NPIX + pixb) * NSLICE;
        for (int i = t; i < 256 * NSLICE; i += 256)
            sSm[i >> 4][i & 15] = smap2[i];
    }
    __syncthreads();

    const float2* vsrc = g_tsing + (size_t)ne * NSLICE * NPIX + pix;

    float aEr[8], aEi[8], aOr[8], aOi[8];
#pragma unroll
    for (int m = 0; m < 8; ++m) { aEr[m] = 0.f; aEi[m] = 0.f; aOr[m] = 0.f; aOi[m] = 0.f; }

#pragma unroll
    for (int z0 = 0; z0 < 8; ++z0) {
        float2 v0 = vsrc[(size_t)z0 * NPIX];
        float2 v8 = vsrc[(size_t)(z0 + 8) * NPIX];
        float2 s0 = sSm[t][z0];
        float2 s8 = sSm[t][z0 + 8];

        float t0r = v0.x * s0.x - v0.y * s0.y;
        float t0i = v0.x * s0.y + v0.y * s0.x;
        float t8r = v8.x * s8.x - v8.y * s8.y;
        float t8i = v8.x * s8.y + v8.y * s8.x;

        float ar  = t0r + t8r, ai = t0i + t8i;
        float bpr = t0r - t8r, bpi = t0i - t8i;
        float2 tw = tws[z0];
        float br = bpr * tw.x - bpi * tw.y;
        float bi = bpr * tw.y + bpi * tw.x;

#pragma unroll
        for (int m = 0; m < 8; ++m) {
            float2 wE = T8s[z0][m];
            aEr[m] = fmaf(ar, wE.x, aEr[m]);  aEr[m] = fmaf(-ai, wE.y, aEr[m]);
            aEi[m] = fmaf(ar, wE.y, aEi[m]);  aEi[m] = fmaf( ai, wE.x, aEi[m]);
            float2 wO = T8[z0][m];
            aOr[m] = fmaf(br, wO.x, aOr[m]);  aOr[m] = fmaf(-bi, wO.y, aOr[m]);
            aOi[m] = fmaf(br, wO.y, aOi[m]);  aOi[m] = fmaf( bi, wO.x, aOi[m]);
        }
    }

#pragma unroll
    for (int m = 0; m < 8; ++m) {
        g_scf[(((size_t)(2 * m) * NCOIL + c) * 12 + ne) * NPIX + pix]
            = make_float2(aEr[m], aEi[m]);
        g_scf[(((size_t)(2 * m + 1) * NCOIL + c) * 12 + ne) * NPIX + pix]
            = make_float2(aOr[m], aOi[m]);
    }
}

// ---------------------------------------------------------------------------
// Phase tables. grid 32, block 384.
// ex kept raw [r][x][p]; ey written as PACKED fp16 A fragments (g_eyA).
// ---------------------------------------------------------------------------
__global__ __launch_bounds__(384)
void exgen_kernel(const float* __restrict__ ktraj)   // [1,32,96,2]
{
    const int r = blockIdx.x;
    const int p = threadIdx.x % NPT;
    const int g = threadIdx.x / NPT;       // 0..3, 16 steps each
    const float w0 = ktraj[(r * NPT + p) * 2 + 0];
    const float w1 = ktraj[(r * NPT + p) * 2 + 1];

    {
        float s, c; sincosf(w0, &s, &c);                      // step exp(-i*w0)
        float pr, pi; sincosf(w0 * (32.0f - g * 16.0f), &pi, &pr);
#pragma unroll 4
        for (int jj = 0; jj < 16; ++jj) {
            int x = g * 16 + jj;
            g_exp_[((size_t)r * IMG + x) * NPT + p] = make_float2(pr, pi);
            float t = pr;
            pr = fmaf(pr, c, pi * s);
            pi = fmaf(pi, c, -(t * s));
        }
    }
    {
        __half2* baseA = (__half2*)(g_eyA + (size_t)r * 1536);
        float s, c; sincosf(w1, &s, &c);
        float pr, pi; sincosf(w1 * (32.0f - g * 16.0f), &pi, &pr);
        float re0 = 0.f, im0 = 0.f;
#pragma unroll
        for (int jj = 0; jj < 16; ++jj) {
            int y = g * 16 + jj;
            if ((jj & 1) == 0) { re0 = pr; im0 = pi; }
            else {
                int y0 = y - 1;
                awrite2g(baseA, p, y0,      __floats2half2_rn(re0, pr));
                awrite2g(baseA, p, 64 + y0, __floats2half2_rn(-im0, -pi));
            }
            float t = pr;
            pr = fmaf(pr, c, pi * s);
            pi = fmaf(pi, c, -(t * s));
        }
    }
}

// ---------------------------------------------------------------------------
// NUFFT via warp-level mma.sync m16n8k16 fp16, ONE ec per block:
//   C[96 x 128] = A[96 x 128] . B^T,  A = [ey.re | -ey.im]  (k = y),
//   B rows: [x]=[re|im], [64+x]=[im|-re]
// grid (32 r, 12 ec), block 512 (16 warps: m2 x n8, 3m x 2n tiles, 8 k16).
// smem 76.5KB -> 2 blocks/SM; 384 blocks -> real co-residency + overlap.
// C (fp32, stride 132) overlays B after the mma.
// ---------------------------------------------------------------------------
#define A_BYTES   24576                 // 1536 uint4
#define B_U2      (16 * 8 * 36)        // 4608 uint2 = 36864 B
#define CSN       132
#define UNION_B   (96 * CSN * 4)       // 50688 B  (>= B bytes)

__global__ __launch_bounds__(512, 2)
void nufft_mma_kernel(const float* __restrict__ ur_list,   // [1,32,4]
                      const int*   __restrict__ sbin,      // [32]
                      float2* __restrict__ out)            // [96,4,32,3]
{
    extern __shared__ unsigned char sh[];
    uint4*   sA4  = (uint4*)sh;
    __half2* sBh  = (__half2*)(sh + A_BYTES);
    const uint2* sB2 = (const uint2*)(sh + A_BYTES);
    float*   sC   = (float*)(sh + A_BYTES);            // overlay on B
    float2*  sPar = (float2*)(sh + A_BYTES + UNION_B); // [96][4]

    const int r    = blockIdx.x;
    const int ec   = blockIdx.y;
    const int e    = ec >> 2;
    const int c    = ec & 3;
    const int tid  = threadIdx.x;
    const int lane = tid & 31;
    const int w    = tid >> 5;      // 0..15
    const int mg   = w >> 3;        // 0..1
    const int ng   = w & 7;         // 0..7

    // ---- copy packed A fragments (24KB linear) ----
    {
        const uint4* srcA = g_eyA + (size_t)r * 1536;
        for (int i = tid; i < 1536; i += 512) sA4[i] = srcA[i];
    }

    // ---- build B (fused Ur mix), fp16 packed fragments ----
    {
        const int kzr = sbin[r];
        const float u0 = ur_list[r * NSING + 0];
        const float u1 = ur_list[r * NSING + 1];
        const float u2 = ur_list[r * NSING + 2];
        const float u3 = ur_list[r * NSING + 3];
        const float2* base = g_scf
            + ((size_t)(kzr * NCOIL + c) * 12 + e) * NPIX;
#pragma unroll
        for (int jj = 0; jj < 4; ++jj) {
            int idx = tid + jj * 512;        // 0..2047 (pixel pairs)
            int x = idx >> 5, jp = idx & 31;
            int ip = x * IMG + 2 * jp;
            float4 v0 = *(const float4*)(base + ip);
            float4 v1 = *(const float4*)(base + ip + 3 * NPIX);
            float4 v2 = *(const float4*)(base + ip + 6 * NPIX);
            float4 v3 = *(const float4*)(base + ip + 9 * NPIX);
            float ar0 = fmaf(u0, v0.x, fmaf(u1, v1.x, fmaf(u2, v2.x, u3 * v3.x)));
            float ai0 = fmaf(u0, v0.y, fmaf(u1, v1.y, fmaf(u2, v2.y, u3 * v3.y)));
            float ar1 = fmaf(u0, v0.z, fmaf(u1, v1.z, fmaf(u2, v2.z, u3 * v3.z)));
            float ai1 = fmaf(u0, v0.w, fmaf(u1, v1.w, fmaf(u2, v2.w, u3 * v3.w)));
            __half2 hre = __floats2half2_rn(ar0, ar1);
            __half2 him = __floats2half2_rn(ai0, ai1);
            __half2 hnr = __floats2half2_rn(-ar0, -ar1);
            int k0 = 2 * jp;
            bwrite2(sBh, x,      k0,      hre);
            bwrite2(sBh, x,      64 + k0, him);
            bwrite2(sBh, 64 + x, k0,      him);
            bwrite2(sBh, 64 + x, 64 + k0, hnr);
        }
    }
    __syncthreads();

    // ---- mma mainloop: K = 128 in 8 k16 steps, 3m x 2n tiles ----
    float d[3][2][4];
#pragma unroll
    for (int mt = 0; mt < 3; ++mt)
#pragma unroll
        for (int nt = 0; nt < 2; ++nt)
#pragma unroll
            for (int q = 0; q < 4; ++q) d[mt][nt][q] = 0.f;

#pragma unroll
    for (int kstep = 0; kstep < 8; ++kstep) {
        uint32_t a[3][4], b[2][2];
#pragma unroll
        for (int mt = 0; mt < 3; ++mt) {
            uint4 av = sA4[(((mg * 3 + mt) * 8 + kstep) << 5) + lane];
            a[mt][0] = av.x; a[mt][1] = av.y; a[mt][2] = av.z; a[mt][3] = av.w;
        }
#pragma unroll
        for (int nt = 0; nt < 2; ++nt) {
            uint2 bv = sB2[((ng * 2 + nt) * 8 + kstep) * 36 + lane];
            b[nt][0] = bv.x; b[nt][1] = bv.y;
        }
#pragma unroll
        for (int mt = 0; mt < 3; ++mt)
#pragma unroll
            for (int nt = 0; nt < 2; ++nt)
                mma_f16(d[mt][nt], a[mt], b[nt]);
    }
    __syncthreads();   // B consumed -> C overlay safe

    // ---- store C (t1): rows p 0..95, cols n 0..127 ----
    {
        const int g  = lane >> 2;
        const int tg = lane & 3;
#pragma unroll
        for (int mt = 0; mt < 3; ++mt) {
#pragma unroll
            for (int nt = 0; nt < 2; ++nt) {
                int p = mg * 48 + mt * 16 + g;
                int n = ng * 16 + nt * 8 + 2 * tg;
                sC[p * CSN + n]           = d[mt][nt][0];
                sC[p * CSN + n + 1]       = d[mt][nt][1];
                sC[(p + 8) * CSN + n]     = d[mt][nt][2];
                sC[(p + 8) * CSN + n + 1] = d[mt][nt][3];
            }
        }
    }
    __syncthreads();

    // ---- ex contraction: thread (p, h) handles x in [16h, 16h+16) ----
    const float2* gex = g_exp_ + (size_t)r * IMG * NPT;
    if (tid < 384) {
        int p = tid % 96, h = tid / 96;          // h 0..3
        float orr = 0.f, oii = 0.f;
        const float* rowp = sC + p * CSN;
#pragma unroll 8
        for (int x = 16 * h; x < 16 * h + 16; ++x) {
            float tr = rowp[x];
            float ti = rowp[64 + x];
            float2 ex = gex[x * NPT + p];
            orr = fmaf(tr,  ex.x, orr);
            orr = fmaf(-ti, ex.y, orr);
            oii = fmaf(tr,  ex.y, oii);
            oii = fmaf(ti,  ex.x, oii);
        }
        sPar[p * 4 + h] = make_float2(orr, oii);
    }
    __syncthreads();

    if (tid < NPT) {
        float2 v0 = sPar[tid * 4 + 0];
        float2 v1 = sPar[tid * 4 + 1];
        float2 v2 = sPar[tid * 4 + 2];
        float2 v3 = sPar[tid * 4 + 3];
        out[((tid * NCOIL + c) * NRO + r) * NECHO + e]
            = make_float2(v0.x + v1.x + v2.x + v3.x,
                          v0.y + v1.y + v2.y + v3.y);
    }
}

// ---------------------------------------------------------------------------
extern "C" void kernel_launch(void* const* d_in, const int* in_sizes, int n_in,
                              void* d_out, int out_size)
{
    const float* singulars = (const float*)d_in[0];
    const float* smap      = (const float*)d_in[1];
    const float* ktraj     = (const float*)d_in[2];
    const float* ur_list   = (const float*)d_in[3];
    const int*   sbin      = (const int*)d_in[4];
    // d_in[5] = dc (unused by the forward reference)

    float2* out = (float2*)d_out;

    const int smemNufft = A_BYTES + UNION_B + 96 * 4 * (int)sizeof(float2); // 78336B
    cudaFuncSetAttribute(nufft_mma_kernel,
                         cudaFuncAttributeMaxDynamicSharedMemorySize, smemNufft);

    transpose_kernel<<<dim3(16, 16), 256>>>(singulars);
    exgen_kernel<<<NRO, 384>>>(ktraj);
    stageA_kernel<<<dim3(16, 48), 256>>>(smap);
    nufft_mma_kernel<<<dim3(NRO, NEC), 512, smemNufft>>>(ur_list, sbin, out);
}